// round 13
// baseline (speedup 1.0000x reference)
#include <cuda_runtime.h>
#include <math.h>

#define BB   32
#define SS   2048
#define DD   512
#define KK   1024   /* 2*EMBEDDING_DIM : GEMM reduction dim */
#define MM   512    /* MODEL_DIM */

#define TS 64       /* s-rows per CTA   */
#define MT 64       /* m-cols per m-iter */
#define KT 32       /* k-chunk           */

/* scratch (static device globals: allowed; no allocation) */
__device__ float g_wq[BB * MM];       /* q@Wa.T + Wa_b + Ua_b  */
__device__ float g_scores[BB * SS];
__device__ float g_attn[BB * SS];
__device__ int   g_mask_is_byte;      /* 1 if mask arrives as 1-byte bool */

/* ------------------------------------------------------------------ */
/* K0: detect mask dtype. Scans first BB*SS bytes (valid under both    */
/* layouts). int32 0/1 values only ever touch byte 0 of each word;     */
/* a byte-bool layout puts random 0/1 in all byte positions.           */
__global__ void detect_mask_kernel(const unsigned int* __restrict__ mask_words)
{
    __shared__ int found;
    if (threadIdx.x == 0) found = 0;
    __syncthreads();
    /* BB*SS bytes = BB*SS/4 words */
    int local = 0;
    for (int i = threadIdx.x; i < BB * SS / 4; i += blockDim.x)
        if (mask_words[i] & 0xFFFFFF00u) local = 1;
    if (local) atomicOr(&found, 1);
    __syncthreads();
    if (threadIdx.x == 0) g_mask_is_byte = found;
}

/* ------------------------------------------------------------------ */
/* K1: wq[b][m] = dot(query[b], Wa_w[m]) + Wa_b[m] + Ua_b[m]          */
__global__ void wq_kernel(const float* __restrict__ query,
                          const float* __restrict__ Wa_w,
                          const float* __restrict__ Wa_b,
                          const float* __restrict__ Ua_b)
{
    __shared__ float q[DD];
    const int b = blockIdx.x;
    for (int i = threadIdx.x; i < DD; i += blockDim.x)
        q[i] = query[b * DD + i];
    __syncthreads();

    for (int m = threadIdx.x; m < MM; m += blockDim.x) {
        const float4* w = (const float4*)(Wa_w + (size_t)m * DD);
        float acc = 0.f;
#pragma unroll 8
        for (int k = 0; k < DD / 4; k++) {
            float4 wv = w[k];
            acc += wv.x * q[4 * k + 0] + wv.y * q[4 * k + 1]
                 + wv.z * q[4 * k + 2] + wv.w * q[4 * k + 3];
        }
        g_wq[b * MM + m] = acc + Wa_b[m] + Ua_b[m];
    }
}

/* ------------------------------------------------------------------ */
/* K2: fused  scores[b][s] = sum_m Va[m] * tanh(wq[b][m] + keys[b,s]·Ua[m]) */
__global__ __launch_bounds__(256)
void scores_kernel(const float* __restrict__ keys,
                   const float* __restrict__ Ua_w,
                   const float* __restrict__ Va_w)
{
    __shared__ float ks[KT][TS];      /* k-major keys tile  (8 KB) */
    __shared__ float us[KT][MT];      /* k-major Ua tile    (8 KB) */
    __shared__ float sc[TS];
    __shared__ float s_bias[MT];
    __shared__ float s_va[MT];

    const int tid = threadIdx.x;
    const int b   = blockIdx.y;
    const int s0  = blockIdx.x * TS;

    if (tid < TS) sc[tid] = 0.f;

    const int tx = tid & 15;          /* m-group (4 cols each)  */
    const int ty = tid >> 4;          /* s-group (4 rows each)  */

    const int lrow = tid & 63;        /* row index for tile loads */
    const int lq   = tid >> 6;        /* 0..3                     */

    const float* keys_b = keys + ((size_t)b * SS + s0) * KK;

    for (int mi = 0; mi < MM / MT; mi++) {
        const int m0 = mi * MT;

        __syncthreads();              /* prior epilogue done reading s_bias/s_va */
        if (tid < MT) {
            s_bias[tid] = g_wq[b * MM + m0 + tid];
            s_va[tid]   = Va_w[m0 + tid];
        }

        float acc[4][4];
#pragma unroll
        for (int i = 0; i < 4; i++)
#pragma unroll
            for (int j = 0; j < 4; j++) acc[i][j] = 0.f;

        for (int kp = 0; kp < KK / KT; kp++) {
            const int k0 = kp * KT;
            __syncthreads();
            /* keys tile -> ks[k][s]  (lane-per-column: conflict-free STS) */
#pragma unroll
            for (int it = 0; it < 2; it++) {
                const int kc = lq * 4 + it * 16;
                float4 v = *(const float4*)(keys_b + (size_t)lrow * KK + k0 + kc);
                ks[kc + 0][lrow] = v.x; ks[kc + 1][lrow] = v.y;
                ks[kc + 2][lrow] = v.z; ks[kc + 3][lrow] = v.w;
            }
            /* Ua tile -> us[k][m] */
#pragma unroll
            for (int it = 0; it < 2; it++) {
                const int kc = lq * 4 + it * 16;
                float4 v = *(const float4*)(Ua_w + (size_t)(m0 + lrow) * KK + k0 + kc);
                us[kc + 0][lrow] = v.x; us[kc + 1][lrow] = v.y;
                us[kc + 2][lrow] = v.z; us[kc + 3][lrow] = v.w;
            }
            __syncthreads();
#pragma unroll
            for (int k = 0; k < KT; k++) {
                float4 a  = *(const float4*)(&ks[k][ty * 4]);
                float4 bb = *(const float4*)(&us[k][tx * 4]);
                float av[4] = { a.x,  a.y,  a.z,  a.w  };
                float bv[4] = { bb.x, bb.y, bb.z, bb.w };
#pragma unroll
                for (int i = 0; i < 4; i++)
#pragma unroll
                    for (int j = 0; j < 4; j++)
                        acc[i][j] += av[i] * bv[j];
            }
        }

        /* epilogue: tanh + Va reduction, fold into per-row score */
#pragma unroll
        for (int i = 0; i < 4; i++) {
            float p = 0.f;
#pragma unroll
            for (int j = 0; j < 4; j++) {
                const int ml = tx * 4 + j;
                p += s_va[ml] * tanhf(s_bias[ml] + acc[i][j]);
            }
            atomicAdd(&sc[ty * 4 + i], p);
        }
    }

    __syncthreads();
    if (tid < TS) g_scores[b * SS + s0 + tid] = sc[tid];
}

/* ------------------------------------------------------------------ */
/* K3a: masked softmax over S per batch (dtype-robust mask read)       */
__global__ void softmax_kernel(const void* __restrict__ mask_raw)
{
    __shared__ float red[256];
    const int b   = blockIdx.x;
    const int tid = threadIdx.x;

    const int is_byte = g_mask_is_byte;
    const unsigned char* m8  = (const unsigned char*)mask_raw;
    const int*           m32 = (const int*)mask_raw;

    /* pass 1: max over unmasked */
    float mx = -1e30f;
    for (int s = tid; s < SS; s += 256) {
        const int masked = is_byte ? (int)m8[b * SS + s] : m32[b * SS + s];
        float v = masked ? -1e30f : g_scores[b * SS + s];
        mx = fmaxf(mx, v);
    }
    red[tid] = mx; __syncthreads();
    for (int o = 128; o > 0; o >>= 1) {
        if (tid < o) red[tid] = fmaxf(red[tid], red[tid + o]);
        __syncthreads();
    }
    mx = red[0];
    __syncthreads();

    /* pass 2: exp + sum */
    float sum = 0.f;
    for (int s = tid; s < SS; s += 256) {
        const int masked = is_byte ? (int)m8[b * SS + s] : m32[b * SS + s];
        float v = masked ? 0.f : expf(g_scores[b * SS + s] - mx);
        g_attn[b * SS + s] = v;
        sum += v;
    }
    red[tid] = sum; __syncthreads();
    for (int o = 128; o > 0; o >>= 1) {
        if (tid < o) red[tid] += red[tid + o];
        __syncthreads();
    }
    const float inv = 1.f / red[0];
    __syncthreads();

    for (int s = tid; s < SS; s += 256)
        g_attn[b * SS + s] *= inv;
}

/* ------------------------------------------------------------------ */
/* K3b: context[b][e] = sum_s attn[b][s] * keys[b][s][e]              */
__global__ __launch_bounds__(256)
void context_kernel(const float* __restrict__ keys, float* __restrict__ out)
{
    __shared__ float w[SS];           /* 8 KB */
    const int b = blockIdx.y;
    const int e = blockIdx.x * 256 + threadIdx.x;

    for (int s = threadIdx.x; s < SS; s += 256)
        w[s] = g_attn[b * SS + s];
    __syncthreads();

    const float* kb = keys + (size_t)b * SS * KK + e;
    float a0 = 0.f, a1 = 0.f, a2 = 0.f, a3 = 0.f;
    for (int s = 0; s < SS; s += 4) {
        a0 += w[s + 0] * kb[(size_t)(s + 0) * KK];
        a1 += w[s + 1] * kb[(size_t)(s + 1) * KK];
        a2 += w[s + 2] * kb[(size_t)(s + 2) * KK];
        a3 += w[s + 3] * kb[(size_t)(s + 3) * KK];
    }
    out[b * KK + e] = (a0 + a1) + (a2 + a3);
}

/* ------------------------------------------------------------------ */
extern "C" void kernel_launch(void* const* d_in, const int* in_sizes, int n_in,
                              void* d_out, int out_size)
{
    const float* query = (const float*)d_in[0];
    const float* keys  = (const float*)d_in[1];
    const void*  mask  = d_in[2];
    const float* Wa_w  = (const float*)d_in[3];
    const float* Wa_b  = (const float*)d_in[4];
    const float* Ua_w  = (const float*)d_in[5];
    const float* Ua_b  = (const float*)d_in[6];
    const float* Va_w  = (const float*)d_in[7];
    /* Va_b (d_in[8]) cancels under softmax */
    float* out = (float*)d_out;

    detect_mask_kernel<<<1, 256>>>((const unsigned int*)mask);

    wq_kernel<<<BB, 256>>>(query, Wa_w, Wa_b, Ua_b);

    dim3 g2(SS / TS, BB);
    scores_kernel<<<g2, 256>>>(keys, Ua_w, Va_w);

    softmax_kernel<<<BB, 256>>>(mask);

    dim3 g3(KK / 256, BB);
    context_kernel<<<g3, 256>>>(keys, out);
}

// round 17
// speedup vs baseline: 2.6609x; 2.6609x over previous
#include <cuda_runtime.h>
#include <cuda_bf16.h>
#include <math.h>
#include <stdint.h>

#define BB   32
#define SS   2048
#define DD   512
#define KK   1024
#define MM   512

#define TSR  128            /* s-rows per CTA   */
#define TNC  128            /* m-cols per CTA   */
#define KC   32             /* k per chunk      */
#define NKC  (KK / KC)      /* 32 chunks        */
#define PITCH 80            /* smem row pitch bytes (64B data + 16B pad) */

/* ---------------- static device scratch (no allocation) ---------------- */
__device__ float g_wq[BB * MM];
__device__ float g_scores[BB * SS];
__device__ float g_attn[BB * SS];
__device__ int   g_mask_is_byte;
__device__ __align__(16) __nv_bfloat16 g_ua_hi[MM * KK];
__device__ __align__(16) __nv_bfloat16 g_ua_lo[MM * KK];

/* ---------------- helpers ----------------- */
__device__ __forceinline__ uint32_t smem_u32(const void* p) {
    uint32_t a;
    asm("{ .reg .u64 t; cvta.to.shared.u64 t, %1; cvt.u32.u64 %0, t; }"
        : "=r"(a) : "l"(p));
    return a;
}
__device__ __forceinline__ uint32_t pack_bf16(float x, float y) {
    __nv_bfloat162 h = __floats2bfloat162_rn(x, y);
    return *reinterpret_cast<uint32_t*>(&h);
}
__device__ __forceinline__ void ldm_x4(uint32_t& r0, uint32_t& r1,
                                       uint32_t& r2, uint32_t& r3, uint32_t a) {
    asm volatile("ldmatrix.sync.aligned.m8n8.x4.shared.b16 {%0,%1,%2,%3}, [%4];"
                 : "=r"(r0), "=r"(r1), "=r"(r2), "=r"(r3) : "r"(a));
}
__device__ __forceinline__ void mma_bf16(float4& c, const uint32_t* a, const uint32_t* b) {
    asm volatile("mma.sync.aligned.m16n8k16.row.col.f32.bf16.bf16.f32 "
                 "{%0,%1,%2,%3}, {%4,%5,%6,%7}, {%8,%9}, {%0,%1,%2,%3};"
                 : "+f"(c.x), "+f"(c.y), "+f"(c.z), "+f"(c.w)
                 : "r"(a[0]), "r"(a[1]), "r"(a[2]), "r"(a[3]), "r"(b[0]), "r"(b[1]));
}
__device__ __forceinline__ void cp_async16(uint32_t dst, const void* src) {
    asm volatile("cp.async.cg.shared.global [%0], [%1], 16;" :: "r"(dst), "l"(src));
}

/* MUFU-free tanh: exp2 via poly + exponent insert; rcp via magic + 3 NR.  */
/* abs error ~1e-7; ~20 FMA/ALU ops, zero MUFU.                            */
__device__ __forceinline__ float fast_tanh(float x) {
    float xc = fminf(fmaxf(x, -10.f), 10.f);
    float z  = xc * 2.8853900817779268f;          /* 2x * log2(e) */
    float nf = z + 12582912.f;                    /* round-to-int magic */
    float n  = nf - 12582912.f;
    float f  = z - n;                             /* f in [-0.5, 0.5] */
    float p  = 0.00015403530393381608f;
    p = fmaf(p, f, 0.0013333558146428443f);
    p = fmaf(p, f, 0.009618129107628477f);
    p = fmaf(p, f, 0.05550410866482158f);
    p = fmaf(p, f, 0.2402265069591007f);
    p = fmaf(p, f, 0.6931471805599453f);
    p = fmaf(p, f, 1.0f);
    /* t = p * 2^n  (low 9 bits of magic float are exactly n)              */
    float t = __int_as_float(__float_as_int(p) + (__float_as_int(nf) << 23));
    float u = t + 1.0f;
    float r = __int_as_float(0x7EF311C3u - __float_as_int(u));
    r = r * fmaf(-u, r, 2.0f);
    r = r * fmaf(-u, r, 2.0f);
    r = r * fmaf(-u, r, 2.0f);
    return (t - 1.0f) * r;
}

/* ------------------------------------------------------------------ */
__global__ void detect_mask_kernel(const unsigned int* __restrict__ mw)
{
    __shared__ int found;
    if (threadIdx.x == 0) found = 0;
    __syncthreads();
    int local = 0;
    for (int i = threadIdx.x; i < BB * SS / 4; i += blockDim.x)
        if (mw[i] & 0xFFFFFF00u) local = 1;
    if (local) atomicOr(&found, 1);
    __syncthreads();
    if (threadIdx.x == 0) g_mask_is_byte = found;
}

/* ------------------------------------------------------------------ */
__global__ void ua_convert_kernel(const float* __restrict__ Ua_w)
{
    int i = blockIdx.x * 256 + threadIdx.x;
    float v = Ua_w[i];
    __nv_bfloat16 h = __float2bfloat16(v);
    g_ua_hi[i] = h;
    g_ua_lo[i] = __float2bfloat16(v - __bfloat162float(h));
}

/* ------------------------------------------------------------------ */
__global__ void zero_scores_kernel()
{
    int i = blockIdx.x * 256 + threadIdx.x;
    if (i < BB * SS) g_scores[i] = 0.f;
}

/* ------------------------------------------------------------------ */
__global__ void wq_kernel(const float* __restrict__ query,
                          const float* __restrict__ Wa_w,
                          const float* __restrict__ Wa_b,
                          const float* __restrict__ Ua_b)
{
    __shared__ float q[DD];
    const int b = blockIdx.x;
    for (int i = threadIdx.x; i < DD; i += blockDim.x)
        q[i] = query[b * DD + i];
    __syncthreads();
    for (int m = threadIdx.x; m < MM; m += blockDim.x) {
        const float4* w = (const float4*)(Wa_w + (size_t)m * DD);
        float acc = 0.f;
#pragma unroll 8
        for (int k = 0; k < DD / 4; k++) {
            float4 wv = w[k];
            acc += wv.x * q[4*k+0] + wv.y * q[4*k+1] + wv.z * q[4*k+2] + wv.w * q[4*k+3];
        }
        g_wq[b * MM + m] = acc + Wa_b[m] + Ua_b[m];
    }
}

/* ------------------------------------------------------------------ */
/* scores via mma.sync bf16 3-split: tile [128 s x 128 m], k-chunks 32 */
__global__ __launch_bounds__(256, 1)
void scores_mma_kernel(const float* __restrict__ keys,
                       const float* __restrict__ Va_w)
{
    __shared__ __align__(128) unsigned char sA_hi[TSR * PITCH];
    __shared__ __align__(128) unsigned char sA_lo[TSR * PITCH];
    __shared__ __align__(128) unsigned char sB_hi[TNC * PITCH];
    __shared__ __align__(128) unsigned char sB_lo[TNC * PITCH];
    __shared__ float bias[TNC];
    __shared__ float va[TNC];
    __shared__ float sc[TSR];

    const int tid  = threadIdx.x;
    const int wid  = tid >> 5;
    const int lane = tid & 31;
    const int mt = blockIdx.x, st = blockIdx.y, b = blockIdx.z;
    const int m0 = mt * TNC, s0 = st * TSR;

    if (tid < TNC) {
        bias[tid] = g_wq[b * MM + m0 + tid];
        va[tid]   = Va_w[m0 + tid];
        sc[tid]   = 0.f;
    }

    const int ws = wid & 3;       /* warp s-block (32 rows) */
    const int wm = wid >> 2;      /* warp m-block (64 cols) */

    const uint32_t a_hi = smem_u32(sA_hi), a_lo = smem_u32(sA_lo);
    const uint32_t b_hi = smem_u32(sB_hi), b_lo = smem_u32(sB_lo);

    float4 C[2][8];
#pragma unroll
    for (int i = 0; i < 2; i++)
#pragma unroll
        for (int j = 0; j < 8; j++) C[i][j] = make_float4(0.f, 0.f, 0.f, 0.f);

    const float* keysb = keys + ((size_t)b * SS + s0) * KK;

    for (int kp = 0; kp < NKC; kp++) {
        const int k0 = kp * KC;
        __syncthreads();          /* previous chunk math done */

        /* B tiles via cp.async (bf16 already, no conversion)            */
#pragma unroll
        for (int it = 0; it < 2; it++) {
            const int q  = tid + it * 256;
            const int r  = q >> 2;
            const int c16 = q & 3;
            const uint32_t off = (uint32_t)(r * PITCH + c16 * 16);
            const size_t gi = (size_t)(m0 + r) * KK + k0 + c16 * 8;
            cp_async16(b_hi + off, g_ua_hi + gi);
            cp_async16(b_lo + off, g_ua_lo + gi);
        }
        asm volatile("cp.async.commit_group;" ::: "memory");

        /* A: keys fp32 -> bf16 hi/lo                                    */
#pragma unroll
        for (int it = 0; it < 4; it++) {
            const int q  = tid + it * 256;
            const int r  = q >> 3;
            const int c4 = q & 7;
            float4 v = *(const float4*)(keysb + (size_t)r * KK + k0 + c4 * 4);
            uint32_t h0 = pack_bf16(v.x, v.y);
            uint32_t h1 = pack_bf16(v.z, v.w);
            __nv_bfloat162 hh0 = *reinterpret_cast<__nv_bfloat162*>(&h0);
            __nv_bfloat162 hh1 = *reinterpret_cast<__nv_bfloat162*>(&h1);
            uint32_t l0 = pack_bf16(v.x - __bfloat162float(hh0.x),
                                    v.y - __bfloat162float(hh0.y));
            uint32_t l1 = pack_bf16(v.z - __bfloat162float(hh1.x),
                                    v.w - __bfloat162float(hh1.y));
            const uint32_t off = (uint32_t)(r * PITCH + c4 * 8);
            *(uint2*)(sA_hi + off) = make_uint2(h0, h1);
            *(uint2*)(sA_lo + off) = make_uint2(l0, l1);
        }
        asm volatile("cp.async.wait_group 0;" ::: "memory");
        __syncthreads();

        /* math: 2 k16 halves x (2 i x 8 j) x 3 splits                   */
#pragma unroll
        for (int kk = 0; kk < 2; kk++) {
            uint32_t ah[2][4], al[2][4];
#pragma unroll
            for (int i = 0; i < 2; i++) {
                const int row = ws * 32 + i * 16 + (lane & 7) + ((lane >> 3) & 1) * 8;
                const int kb  = kk * 2 + (lane >> 4);
                const uint32_t off = (uint32_t)(row * PITCH + kb * 16);
                ldm_x4(ah[i][0], ah[i][1], ah[i][2], ah[i][3], a_hi + off);
                ldm_x4(al[i][0], al[i][1], al[i][2], al[i][3], a_lo + off);
            }
            uint32_t bh[8][2], bl[8][2];
#pragma unroll
            for (int j2 = 0; j2 < 4; j2++) {
                const int row = wm * 64 + j2 * 16 + ((lane >> 4) & 1) * 8 + (lane & 7);
                const int kb  = kk * 2 + ((lane >> 3) & 1);
                const uint32_t off = (uint32_t)(row * PITCH + kb * 16);
                uint32_t r0, r1, r2, r3;
                ldm_x4(r0, r1, r2, r3, b_hi + off);
                bh[j2*2][0] = r0; bh[j2*2][1] = r1;
                bh[j2*2+1][0] = r2; bh[j2*2+1][1] = r3;
                ldm_x4(r0, r1, r2, r3, b_lo + off);
                bl[j2*2][0] = r0; bl[j2*2][1] = r1;
                bl[j2*2+1][0] = r2; bl[j2*2+1][1] = r3;
            }
#pragma unroll
            for (int i = 0; i < 2; i++)
#pragma unroll
                for (int j = 0; j < 8; j++) {
                    mma_bf16(C[i][j], ah[i], bh[j]);
                    mma_bf16(C[i][j], ah[i], bl[j]);
                    mma_bf16(C[i][j], al[i], bh[j]);
                }
        }
    }

    /* epilogue: tanh + Va partial reduction over this CTA's 128 m-cols  */
    {
        const int tg = lane >> 2;     /* row within 8  */
        const int tn = lane & 3;      /* col pair      */
        float accr[4] = {0.f, 0.f, 0.f, 0.f};
#pragma unroll
        for (int i = 0; i < 2; i++) {
#pragma unroll
            for (int j = 0; j < 8; j++) {
                const int mc = wm * 64 + j * 8 + tn * 2;
                float2 bv = *(const float2*)&bias[mc];
                float2 vv = *(const float2*)&va[mc];
                float4 c  = C[i][j];
                accr[i*2+0] += vv.x * fast_tanh(bv.x + c.x)
                             + vv.y * fast_tanh(bv.y + c.y);
                accr[i*2+1] += vv.x * fast_tanh(bv.x + c.z)
                             + vv.y * fast_tanh(bv.y + c.w);
            }
        }
        atomicAdd(&sc[ws * 32 + 0 * 16 + tg + 0], accr[0]);
        atomicAdd(&sc[ws * 32 + 0 * 16 + tg + 8], accr[1]);
        atomicAdd(&sc[ws * 32 + 1 * 16 + tg + 0], accr[2]);
        atomicAdd(&sc[ws * 32 + 1 * 16 + tg + 8], accr[3]);
    }
    __syncthreads();
    if (tid < TSR)
        atomicAdd(&g_scores[b * SS + s0 + tid], sc[tid]);
}

/* ------------------------------------------------------------------ */
__global__ void softmax_kernel(const void* __restrict__ mask_raw)
{
    __shared__ float red[256];
    const int b = blockIdx.x, tid = threadIdx.x;
    const int is_byte = g_mask_is_byte;
    const unsigned char* m8  = (const unsigned char*)mask_raw;
    const int*           m32 = (const int*)mask_raw;

    float mx = -1e30f;
    for (int s = tid; s < SS; s += 256) {
        const int masked = is_byte ? (int)m8[b * SS + s] : m32[b * SS + s];
        mx = fmaxf(mx, masked ? -1e30f : g_scores[b * SS + s]);
    }
    red[tid] = mx; __syncthreads();
    for (int o = 128; o > 0; o >>= 1) {
        if (tid < o) red[tid] = fmaxf(red[tid], red[tid + o]);
        __syncthreads();
    }
    mx = red[0]; __syncthreads();

    float sum = 0.f;
    for (int s = tid; s < SS; s += 256) {
        const int masked = is_byte ? (int)m8[b * SS + s] : m32[b * SS + s];
        float v = masked ? 0.f : expf(g_scores[b * SS + s] - mx);
        g_attn[b * SS + s] = v;
        sum += v;
    }
    red[tid] = sum; __syncthreads();
    for (int o = 128; o > 0; o >>= 1) {
        if (tid < o) red[tid] += red[tid + o];
        __syncthreads();
    }
    const float inv = 1.f / red[0]; __syncthreads();

    for (int s = tid; s < SS; s += 256)
        g_attn[b * SS + s] *= inv;
}

/* ------------------------------------------------------------------ */
__global__ __launch_bounds__(256)
void context_kernel(const float* __restrict__ keys, float* __restrict__ out)
{
    __shared__ float w[SS];
    const int b = blockIdx.y;
    const int e = blockIdx.x * 256 + threadIdx.x;

    for (int s = threadIdx.x; s < SS; s += 256)
        w[s] = g_attn[b * SS + s];
    __syncthreads();

    const float* kb = keys + (size_t)b * SS * KK + e;
    float a0 = 0.f, a1 = 0.f, a2 = 0.f, a3 = 0.f;
    for (int s = 0; s < SS; s += 4) {
        a0 += w[s + 0] * kb[(size_t)(s + 0) * KK];
        a1 += w[s + 1] * kb[(size_t)(s + 1) * KK];
        a2 += w[s + 2] * kb[(size_t)(s + 2) * KK];
        a3 += w[s + 3] * kb[(size_t)(s + 3) * KK];
    }
    out[b * KK + e] = (a0 + a1) + (a2 + a3);
}

/* ------------------------------------------------------------------ */
extern "C" void kernel_launch(void* const* d_in, const int* in_sizes, int n_in,
                              void* d_out, int out_size)
{
    const float* query = (const float*)d_in[0];
    const float* keys  = (const float*)d_in[1];
    const void*  mask  = d_in[2];
    const float* Wa_w  = (const float*)d_in[3];
    const float* Wa_b  = (const float*)d_in[4];
    const float* Ua_w  = (const float*)d_in[5];
    const float* Ua_b  = (const float*)d_in[6];
    const float* Va_w  = (const float*)d_in[7];
    float* out = (float*)d_out;

    detect_mask_kernel<<<1, 256>>>((const unsigned int*)mask);
    ua_convert_kernel<<<MM * KK / 256, 256>>>(Ua_w);
    wq_kernel<<<BB, 256>>>(query, Wa_w, Wa_b, Ua_b);
    zero_scores_kernel<<<BB * SS / 256, 256>>>();

    dim3 g2(MM / TNC, SS / TSR, BB);   /* (4, 16, 32) */
    scores_mma_kernel<<<g2, 256>>>(keys, Va_w);

    softmax_kernel<<<BB, 256>>>(mask);

    dim3 g3(KK / 256, BB);
    context_kernel<<<g3, 256>>>(keys, out);
}